// round 3
// baseline (speedup 1.0000x reference)
#include <cuda_runtime.h>

// MomentumLIF: N=64, T=64, D=8192
//   v_t = mom * v_{t-1} + x_t - lamb * u_{t-1}
//   u_t = 0.5 * u_{t-1} + v_t
//   s_t = (u_t >= 1.0); u_t = 0 if spiked
//
// R2 change: float2 per thread (262144 threads -> ~86%% occupancy vs 43%%)
// plus explicit one-step load prefetch and streaming cache hints.

#define N_ 64
#define T_ 64
#define D_ 8192
#define DECAY_ 0.5f
#define TH_ 1.0f

__global__ __launch_bounds__(256)
void momentum_lif_kernel(const float* __restrict__ x,
                         const float* __restrict__ mom_p,
                         const float* __restrict__ lamb_p,
                         float* __restrict__ out)
{
    const int vecD = D_ / 2;                 // 4096 float2 per (n,t) row
    const int vid = blockIdx.x * blockDim.x + threadIdx.x;   // over N*vecD
    const int n  = vid >> 12;                // vid / 4096
    const int dv = vid & (vecD - 1);

    const float mom = __ldg(mom_p);
    const float lb  = __ldg(lamb_p);

    const float2* xin  = reinterpret_cast<const float2*>(x)  + (size_t)n * T_ * vecD + dv;
    float2*       oout = reinterpret_cast<float2*>(out)       + (size_t)n * T_ * vecD + dv;

    float u0 = 0.f, u1 = 0.f;
    float v0 = 0.f, v1 = 0.f;

    // prefetch t=0
    float2 xt = __ldcs(xin);

    #pragma unroll
    for (int t = 0; t < T_; ++t) {
        // prefetch next timestep before touching the recurrence
        float2 xnext;
        if (t + 1 < T_) xnext = __ldcs(xin + (size_t)(t + 1) * vecD);

        v0 = mom * v0 + xt.x - lb * u0;
        v1 = mom * v1 + xt.y - lb * u1;

        u0 = DECAY_ * u0 + v0;
        u1 = DECAY_ * u1 + v1;

        float2 s;
        s.x = (u0 >= TH_) ? 1.0f : 0.0f;
        s.y = (u1 >= TH_) ? 1.0f : 0.0f;

        u0 = (u0 >= TH_) ? 0.0f : u0;
        u1 = (u1 >= TH_) ? 0.0f : u1;

        __stcs(oout + (size_t)t * vecD, s);

        xt = xnext;
    }
}

extern "C" void kernel_launch(void* const* d_in, const int* in_sizes, int n_in,
                              void* d_out, int out_size)
{
    const float* x    = (const float*)d_in[0];
    const float* mom  = (const float*)d_in[1];
    const float* lamb = (const float*)d_in[2];
    float* out        = (float*)d_out;

    const int total_vec = N_ * (D_ / 2);     // 262144 threads
    const int threads = 256;
    const int blocks = total_vec / threads;  // 1024

    momentum_lif_kernel<<<blocks, threads>>>(x, mom, lamb, out);
}